// round 15
// baseline (speedup 1.0000x reference)
#include <cuda_runtime.h>
#include <cuda_bf16.h>
#include <mma.h>
#include <cstdint>
using namespace nvcuda;

#define BATCH   2
#define SEQ     2048
#define DMODEL  768
#define INTER   1536
#define NHEADS  24
#define HEADDIM 64
#define DSTATE  128
#define CONVD   1792
#define PROJD   3352
#define CHUNK   256
#define NCHUNK  8
#define BS      (BATCH*SEQ)   // 4096

#define PROJD_PAD 3456        // 27*128 (padded N for proj GEMM)
#define PROJ_LD   PROJD_PAD   // row stride of g_proj
#define K3P (3*DMODEL)        // 2304
#define K3O (3*INTER)         // 4608

// ---------------- scratch (static device globals; no allocs allowed) ----------------
__device__ __align__(256) float g_proj [(long)BS*PROJ_LD];   // padded stride!
__device__ __align__(256) float g_xraw [(long)BS*INTER];
__device__ __align__(256) float g_xdisc[(long)BS*INTER];
__device__ __align__(256) float g_Bm   [(long)BS*DSTATE];
__device__ __align__(256) float g_Cm   [(long)BS*DSTATE];
__device__ float g_dt   [(long)BS*NHEADS];
__device__ float g_acum [(long)BATCH*NHEADS*NCHUNK*CHUNK];
__device__ __align__(256) float g_G    [(long)BATCH*NCHUNK*CHUNK*CHUNK];
__device__ __align__(256) float g_S    [(long)BATCH*NCHUNK*NHEADS*HEADDIM*DSTATE];
__device__ __align__(256) float g_pr   [(long)BATCH*NCHUNK*NHEADS*HEADDIM*DSTATE];
__device__ __align__(256) float g_y    [(long)BS*INTER];
// bf16 split operand buffers
__device__ __align__(256) __nv_bfloat16 g_Ah3[(long)BS*K3P];        // A: [hi, lo, hi]
__device__ __align__(256) __nv_bfloat16 g_Bh3[(long)PROJD_PAD*K3P]; // B: [hi, hi, lo]
__device__ __align__(256) __nv_bfloat16 g_Ao3[(long)BS*K3O];        // A: [hi, lo, hi]
__device__ __align__(256) __nv_bfloat16 g_Bo3[(long)DMODEL*K3O];    // B: [hi, hi, lo]

// ================= packed fp32x2 helpers (Blackwell FFMA2) ==========================
__device__ __forceinline__ uint64_t pack2(float x) {
    uint64_t r; asm("mov.b64 %0, {%1, %1};" : "=l"(r) : "f"(x)); return r;
}
__device__ __forceinline__ void fma2(uint64_t& d, uint64_t a, uint64_t b) {
    asm("fma.rn.f32x2 %0, %1, %2, %0;" : "+l"(d) : "l"(a), "l"(b));
}
__device__ __forceinline__ void mul2(uint64_t& d, uint64_t a) {
    asm("mul.rn.f32x2 %0, %0, %1;" : "+l"(d) : "l"(a));
}
__device__ __forceinline__ float2 unpack2(uint64_t v) {
    float2 f; asm("mov.b64 {%0, %1}, %2;" : "=f"(f.x), "=f"(f.y) : "l"(v)); return f;
}

// ================= cp.async helpers (sm_80+) ========================================
__device__ __forceinline__ uint32_t smem_u32(const void* p) {
    uint32_t a;
    asm("{ .reg .u64 t0; cvta.to.shared.u64 t0, %1; cvt.u32.u64 %0, t0; }"
        : "=r"(a) : "l"(p));
    return a;
}
#define CP16(dst, src) \
    asm volatile("cp.async.cg.shared.global [%0], [%1], 16;" :: "r"(dst), "l"(src))
#define CP_COMMIT() asm volatile("cp.async.commit_group;")
#define CP_WAIT(n)  asm volatile("cp.async.wait_group %0;" :: "n"(n))

// ================= wmma GEMM (R8-proven config, best measured) ======================
#define LDAE 72
#define TROWB 144
#define TILE_B (128*TROWB)             // 18432
#define GEMM_SMEM (4*TILE_B)           // 73728
#define GEMM_THREADS 256

__device__ __forceinline__ void stage_tile(uint32_t sa, uint32_t sb,
                                           const __nv_bfloat16* Ab,
                                           const __nv_bfloat16* Bb,
                                           int K3, int t) {
#pragma unroll
    for (int i = 0; i < 4; i++) {
        int id = i * GEMM_THREADS + t; // 0..1023 = 128 rows x 8 segs
        int row = id >> 3, seg = id & 7;
        uint32_t so = row * TROWB + seg * 16;
        CP16(sa + so, Ab + (long)row * K3 + seg * 8);
        CP16(sb + so, Bb + (long)row * K3 + seg * 8);
    }
}

__global__ void __launch_bounds__(GEMM_THREADS)
wmma_gemm(const __nv_bfloat16* __restrict__ A, const __nv_bfloat16* __restrict__ B,
          float* __restrict__ C, int K3, int KT, int ldc) {
    extern __shared__ char smem[];
    uint32_t sbase = smem_u32(smem);
    int t = threadIdx.x, wid = t >> 5;
    int wm = wid & 3, wn = wid >> 2;
    int m0 = blockIdx.y * 128, n0 = blockIdx.x * 128;

    wmma::fragment<wmma::accumulator, 16, 16, 16, float> cf[2][4];
#pragma unroll
    for (int mi = 0; mi < 2; mi++)
#pragma unroll
        for (int ni = 0; ni < 4; ni++) wmma::fill_fragment(cf[mi][ni], 0.f);

    stage_tile(sbase, sbase + TILE_B, A + (long)m0 * K3, B + (long)n0 * K3, K3, t);
    CP_COMMIT();

    for (int kt = 0; kt < KT; kt++) {
        int buf = kt & 1;
        if (kt + 1 < KT) {
            uint32_t sa = sbase + (buf ^ 1) * 2 * TILE_B;
            stage_tile(sa, sa + TILE_B,
                       A + (long)m0 * K3 + (kt + 1) * 64,
                       B + (long)n0 * K3 + (kt + 1) * 64, K3, t);
            CP_COMMIT();
            CP_WAIT(1);
        } else {
            CP_WAIT(0);
        }
        __syncthreads();

        const __nv_bfloat16* sa = (const __nv_bfloat16*)(smem + buf * 2 * TILE_B);
        const __nv_bfloat16* sb = (const __nv_bfloat16*)(smem + buf * 2 * TILE_B + TILE_B);
#pragma unroll
        for (int ks = 0; ks < 4; ks++) {
            wmma::fragment<wmma::matrix_a, 16, 16, 16, __nv_bfloat16, wmma::row_major> af[2];
            wmma::fragment<wmma::matrix_b, 16, 16, 16, __nv_bfloat16, wmma::col_major> bf[4];
#pragma unroll
            for (int mi = 0; mi < 2; mi++)
                wmma::load_matrix_sync(af[mi], sa + (wm * 32 + mi * 16) * LDAE + ks * 16, LDAE);
#pragma unroll
            for (int ni = 0; ni < 4; ni++)
                wmma::load_matrix_sync(bf[ni], sb + (wn * 64 + ni * 16) * LDAE + ks * 16, LDAE);
#pragma unroll
            for (int mi = 0; mi < 2; mi++)
#pragma unroll
                for (int ni = 0; ni < 4; ni++)
                    wmma::mma_sync(cf[mi][ni], af[mi], bf[ni], cf[mi][ni]);
        }
        __syncthreads();
    }

#pragma unroll
    for (int mi = 0; mi < 2; mi++)
#pragma unroll
        for (int ni = 0; ni < 4; ni++)
            wmma::store_matrix_sync(
                C + (long)(m0 + wm * 32 + mi * 16) * ldc + n0 + wn * 64 + ni * 16,
                cf[mi][ni], ldc, wmma::mem_row_major);
}

// ---------------- fp32 -> bf16 split conversions ------------------------------------
__global__ void cvt3a_kernel(const float* __restrict__ src, __nv_bfloat16* __restrict__ dst,
                             int rowsValid, int K) {
    long idx = (long)blockIdx.x * 256 + threadIdx.x;
    int r = (int)(idx / K), k = (int)(idx % K);
    float v = (r < rowsValid) ? src[(long)r * K + k] : 0.f;
    __nv_bfloat16 hi = __float2bfloat16(v);
    __nv_bfloat16 lo = __float2bfloat16(v - __bfloat162float(hi));
    long base = (long)r * (3 * K) + k;
    dst[base] = hi; dst[base + K] = lo; dst[base + 2 * K] = hi;
}
__global__ void cvt3b_kernel(const float* __restrict__ src, __nv_bfloat16* __restrict__ dst,
                             int rowsValid, int K) {
    long idx = (long)blockIdx.x * 256 + threadIdx.x;
    int r = (int)(idx / K), k = (int)(idx % K);
    float v = (r < rowsValid) ? src[(long)r * K + k] : 0.f;
    __nv_bfloat16 hi = __float2bfloat16(v);
    __nv_bfloat16 lo = __float2bfloat16(v - __bfloat162float(hi));
    long base = (long)r * (3 * K) + k;
    dst[base] = hi; dst[base + K] = hi; dst[base + 2 * K] = lo;
}

// ---------------- fp32 SGEMM (kept for the small G = C@B^T) -------------------------
__device__ __forceinline__ void sgemm_body(const float* __restrict__ A,
                                           const float* __restrict__ Bm,
                                           float* __restrict__ C,
                                           int M, int N, int Kd) {
    __shared__ float As[16][64];
    __shared__ float Bs[16][64];
    int t  = threadIdx.x;
    int tx = t & 15, ty = t >> 4;
    int row0 = blockIdx.y * 64, col0 = blockIdx.x * 64;
    int lr = t >> 2, lc = (t & 3) << 2;
    float acc[4][4] = {};
    for (int k0 = 0; k0 < Kd; k0 += 16) {
        int ar = row0 + lr;
        float4 av = make_float4(0.f, 0.f, 0.f, 0.f);
        if (ar < M) av = *(const float4*)(A + (long)ar * Kd + k0 + lc);
        As[lc][lr] = av.x; As[lc+1][lr] = av.y; As[lc+2][lr] = av.z; As[lc+3][lr] = av.w;
        int br = col0 + lr;
        float4 bv = make_float4(0.f, 0.f, 0.f, 0.f);
        if (br < N) bv = *(const float4*)(Bm + (long)br * Kd + k0 + lc);
        Bs[lc][lr] = bv.x; Bs[lc+1][lr] = bv.y; Bs[lc+2][lr] = bv.z; Bs[lc+3][lr] = bv.w;
        __syncthreads();
#pragma unroll
        for (int kk = 0; kk < 16; kk++) {
            float4 a4 = *(const float4*)&As[kk][ty * 4];
            float4 b4 = *(const float4*)&Bs[kk][tx * 4];
            float a[4] = {a4.x, a4.y, a4.z, a4.w};
            float b[4] = {b4.x, b4.y, b4.z, b4.w};
#pragma unroll
            for (int i = 0; i < 4; i++)
#pragma unroll
                for (int j = 0; j < 4; j++) acc[i][j] += a[i] * b[j];
        }
        __syncthreads();
    }
#pragma unroll
    for (int i = 0; i < 4; i++) {
        int r = row0 + ty * 4 + i;
        if (r >= M) continue;
#pragma unroll
        for (int j = 0; j < 4; j++) {
            int cc = col0 + tx * 4 + j;
            if (cc < N) C[(long)r * N + cc] = acc[i][j];
        }
    }
}
__global__ void k_G_gemm() {
    long off = (long)blockIdx.z * CHUNK * DSTATE;
    sgemm_body(g_Cm + off, g_Bm + off, g_G + (long)blockIdx.z * CHUNK * CHUNK,
               CHUNK, CHUNK, DSTATE);
}

// ---------------- dt (softplus+clip) + per-chunk inclusive cumsum of A*dt -----------
__global__ void dtscan_kernel(const float* __restrict__ dt_bias,
                              const float* __restrict__ A_log) {
    int bid = blockIdx.x;                 // ((b*NHEADS + h)*NCHUNK + c)
    int c = bid % NCHUNK;
    int h = (bid / NCHUNK) % NHEADS;
    int b = bid / (NCHUNK * NHEADS);
    int l = threadIdx.x;
    int s = c * CHUNK + l;
    float dtraw = g_proj[((long)(b * SEQ + s)) * PROJ_LD + (INTER + CONVD) + h];
    float xx = dtraw + dt_bias[h];
    float sp = (xx > 20.f) ? xx : log1pf(expf(xx));
    float dtv = fminf(fmaxf(sp, 0.001f), 0.1f);
    g_dt[(b * SEQ + s) * NHEADS + h] = dtv;
    float a = -expf(A_log[h]) * dtv;

    __shared__ float buf[256];
    buf[l] = a; __syncthreads();
    float v = a;
    for (int off = 1; off < 256; off <<= 1) {
        float add = (l >= off) ? buf[l - off] : 0.f;
        __syncthreads();
        v += add; buf[l] = v;
        __syncthreads();
    }
    g_acum[(long)bid * CHUNK + l] = v;
}

// ---------------- depthwise causal conv (K=4) + bias + silu, split outputs ---------
__global__ void conv_kernel(const float* __restrict__ conv_w,
                            const float* __restrict__ conv_b) {
    int bs = blockIdx.x;                  // 0..4095
    int ch = blockIdx.y * 256 + threadIdx.x;
    int b = bs >> 11, s = bs & 2047;
    float acc = conv_b[ch];
#pragma unroll
    for (int k = 0; k < 4; k++) {
        int sp = s - 3 + k;
        if (sp >= 0)
            acc += g_proj[((long)(b * SEQ + sp)) * PROJ_LD + INTER + ch] * conv_w[ch * 4 + k];
    }
    float v = acc / (1.f + __expf(-acc));   // silu
    if (ch < INTER) {
        g_xraw[(long)bs * INTER + ch] = v;
        int h = ch >> 6;
        g_xdisc[(long)bs * INTER + ch] = v * g_dt[bs * NHEADS + h];
    } else if (ch < INTER + DSTATE) {
        g_Bm[(long)bs * DSTATE + (ch - INTER)] = v;
    } else {
        g_Cm[(long)bs * DSTATE + (ch - INTER - DSTATE)] = v;
    }
}

// ---------------- chunk states (LDS.128 + dual FFMA2) -------------------------------
__global__ void states_kernel() {
    int bid = blockIdx.x;                 // ((b*NCHUNK + c)*NHEADS + h)
    int h = bid % NHEADS;
    int c = (bid / NHEADS) % NCHUNK;
    int b = bid / (NHEADS * NCHUNK);
    int t = threadIdx.x;
    __shared__ __align__(16) float xs[32 * 64];
    __shared__ float bss[32 * 128];
    __shared__ float sdec[256];
    {
        const float* ac = g_acum + ((long)((b * NHEADS + h) * NCHUNK + c)) * CHUNK;
        float aend = ac[CHUNK - 1];
        sdec[t] = __expf(aend - ac[t]);
    }
    uint64_t acc2[16];
#pragma unroll
    for (int i = 0; i < 16; i++) acc2[i] = 0ull;
    int n = t & 127;
    int p0 = (t >> 7) << 5;               // 0 or 32
    long sBase = (long)(b * SEQ + c * CHUNK);
    for (int lt = 0; lt < 8; lt++) {
        __syncthreads();
#pragma unroll
        for (int it = 0; it < 8; it++) {  // x tile 32x64
            int e = it * 256 + t; int r = e >> 6, cc = e & 63;
            xs[e] = g_xdisc[(sBase + lt * 32 + r) * INTER + h * 64 + cc];
        }
#pragma unroll
        for (int it = 0; it < 16; it++) { // B tile 32x128
            int e = it * 256 + t; int r = e >> 7, cc = e & 127;
            bss[e] = g_Bm[(sBase + lt * 32 + r) * DSTATE + cc];
        }
        __syncthreads();
#pragma unroll
        for (int ll = 0; ll < 32; ll++) {
            uint64_t w2 = pack2(bss[ll * 128 + n] * sdec[lt * 32 + ll]);
            const ulonglong2* xr = (const ulonglong2*)&xs[ll * 64 + p0];
#pragma unroll
            for (int i = 0; i < 8; i++) {
                ulonglong2 v = xr[i];                 // one LDS.128 = two f32x2
                fma2(acc2[2 * i],     w2, v.x);
                fma2(acc2[2 * i + 1], w2, v.y);
            }
        }
    }
    float* outp = g_S + (long)bid * HEADDIM * DSTATE;
#pragma unroll
    for (int i = 0; i < 16; i++) {
        float2 f = unpack2(acc2[i]);
        outp[(p0 + 2 * i) * DSTATE + n]     = f.x;
        outp[(p0 + 2 * i + 1) * DSTATE + n] = f.y;
    }
}

// ---------------- chunk recurrence: P[c] = S[c-1] + exp(Aend[c-1]) * P[c-1] ---------
__global__ void recur_kernel() {
    int bid = blockIdx.x;                 // b*NHEADS + h
    int h = bid % NHEADS, b = bid / NHEADS;
    int t = threadIdx.x;
    float pr[32];
#pragma unroll
    for (int j = 0; j < 32; j++) pr[j] = 0.f;
    for (int c = 0; c < NCHUNK; c++) {
        long base = ((long)((b * NCHUNK + c) * NHEADS + h)) * (HEADDIM * DSTATE);
#pragma unroll
        for (int j = 0; j < 32; j++) g_pr[base + j * 256 + t] = pr[j];
        float lam = __expf(g_acum[((long)((b * NHEADS + h) * NCHUNK + c)) * CHUNK + 255]);
#pragma unroll
        for (int j = 0; j < 32; j++) pr[j] = g_S[base + j * 256 + t] + lam * pr[j];
    }
}

// ---------------- combine, p-split 2-way: each block does 32 of 64 head-dims --------
// Halved accumulator state (16 u64) + smaller tiles -> ~70 regs, 3-4 CTAs/SM,
// 768 blocks. Cs/Gs tiles are loaded by both p-halves (L2-resident).
__global__ void combine_kernel(const float* __restrict__ Dparam) {
    int bid = blockIdx.x;                 // (((b*NCHUNK + c)*NHEADS + h)*2 + ph)
    int ph = bid & 1;
    int rest = bid >> 1;
    int h = rest % NHEADS;
    int c = (rest / NHEADS) % NCHUNK;
    int b = rest / (NHEADS * NCHUNK);
    int l = threadIdx.x;
    int pbase = ph * 32;
    __shared__ float sAc[256];
    __shared__ __align__(16) float sbuf[9472];  // ph1: Cs 4352 + Ps 512; ph2: Gs 8448 + xs 1024
    __shared__ float tExp[32];
    const float* ac = g_acum + ((long)((b * NHEADS + h) * NCHUNK + c)) * CHUNK;
    sAc[l] = ac[l];
    __syncthreads();

    uint64_t acc2[16];
#pragma unroll
    for (int i = 0; i < 16; i++) acc2[i] = 0ull;
    long sBase  = (long)(b * SEQ + c * CHUNK);
    long prBase = ((long)((b * NCHUNK + c) * NHEADS + h)) * (HEADDIM * DSTATE);

    // ---- Phase 1: Y_off raw = C_row(l) . prior[pbase+p,:] ----
    float* Cs = sbuf;                     // [256][17]
    float* Ps = sbuf + 4352;              // [16][32] (16B-aligned)
    for (int nt = 0; nt < 8; nt++) {
        int n0 = nt * 16;
        __syncthreads();
#pragma unroll
        for (int it = 0; it < 16; it++) { // C tile 256x16
            int e = it * 256 + l; int r = e >> 4, cc = e & 15;
            Cs[r * 17 + cc] = g_Cm[(sBase + r) * DSTATE + n0 + cc];
        }
#pragma unroll
        for (int it = 0; it < 2; it++) {  // prior^T tile 16x32 (this p-half)
            int e = it * 256 + l; int nn = e >> 5, p = e & 31;
            Ps[nn * 32 + p] = g_pr[prBase + (pbase + p) * DSTATE + n0 + nn];
        }
        __syncthreads();
#pragma unroll
        for (int nn = 0; nn < 16; nn++) {
            uint64_t cv2 = pack2(Cs[l * 17 + nn]);
            const ulonglong2* pp = (const ulonglong2*)&Ps[nn * 32];
#pragma unroll
            for (int i = 0; i < 8; i++) {
                ulonglong2 v = pp[i];
                fma2(acc2[2 * i],     cv2, v.x);
                fma2(acc2[2 * i + 1], cv2, v.y);
            }
        }
    }
    {   // scale by state_decay_out = exp(Acum[l])
        uint64_t el2 = pack2(__expf(sAc[l]));
#pragma unroll
        for (int i = 0; i < 16; i++) mul2(acc2[i], el2);
    }

    // ---- Phase 2: Y_diag, L factored per s-tile ----
    float* Gs = sbuf;                     // [256][33]
    float* xs = sbuf + 8448;              // [32][32] (16B-aligned)
    const float* Grow = g_G + ((long)(b * NCHUNK + c)) * CHUNK * CHUNK;
    for (int st = 0; st < 8; st++) {
        int s0 = st * 32;
        __syncthreads();
#pragma unroll
        for (int it = 0; it < 32; it++) { // G tile 256x32
            int e = it * 256 + l; int r = e >> 5, cc = e & 31;
            Gs[r * 33 + cc] = Grow[(long)r * CHUNK + s0 + cc];
        }
#pragma unroll
        for (int it = 0; it < 4; it++) {  // x tile 32x32 (this p-half)
            int e = it * 256 + l; int r = e >> 5, cc = e & 31;
            xs[e] = g_xdisc[(sBase + s0 + r) * INTER + h * 64 + pbase + cc];
        }
        if (l < 32) tExp[l] = __expf(sAc[s0] - sAc[s0 + l]);
        __syncthreads();
        if (l >= s0) {
            float basee = __expf(sAc[l] - sAc[s0]);
            int jmax = min(32, l - s0 + 1);
            for (int j = 0; j < jmax; j++) {
                uint64_t w2 = pack2(Gs[l * 33 + j] * basee * tExp[j]);
                const ulonglong2* xr = (const ulonglong2*)&xs[j * 32];
#pragma unroll
                for (int i = 0; i < 8; i++) {
                    ulonglong2 v = xr[i];
                    fma2(acc2[2 * i],     w2, v.x);
                    fma2(acc2[2 * i + 1], w2, v.y);
                }
            }
        }
    }

    // ---- D residual + store (this p-half) ----
    uint64_t Dh2 = pack2(Dparam[h]);
    const ulonglong2* xr2 = (const ulonglong2*)(g_xraw + (sBase + l) * INTER + h * 64 + pbase);
    ulonglong2* yout2 = (ulonglong2*)(g_y + (sBase + l) * INTER + h * 64 + pbase);
#pragma unroll
    for (int i = 0; i < 8; i++) {
        ulonglong2 xv = xr2[i];
        uint64_t a0 = acc2[2 * i], a1 = acc2[2 * i + 1];
        fma2(a0, Dh2, xv.x);
        fma2(a1, Dh2, xv.y);
        ulonglong2 o; o.x = a0; o.y = a1;
        yout2[i] = o;
    }
}

// ---------------- gated RMSNorm -> bf16 A-split ([hi,lo,hi]) into g_Ao3 -------------
__global__ void norm_kernel(const float* __restrict__ norm_w) {
    int bs = blockIdx.x;
    int t = threadIdx.x;
    __shared__ float red[256];
    float yf[6];
    float ss = 0.f;
#pragma unroll
    for (int i = 0; i < 6; i++) {
        int idx = t + i * 256;
        float yv = g_y[(long)bs * INTER + idx];
        float gv = g_proj[(long)bs * PROJ_LD + idx];
        float f = yv * (gv / (1.f + __expf(-gv)));
        yf[i] = f; ss += f * f;
    }
    red[t] = ss; __syncthreads();
    for (int off = 128; off > 0; off >>= 1) {
        if (t < off) red[t] += red[t + off];
        __syncthreads();
    }
    float scale = rsqrtf(red[0] / (float)INTER + 1e-5f);
#pragma unroll
    for (int i = 0; i < 6; i++) {
        int idx = t + i * 256;
        float v = yf[i] * scale * norm_w[idx];
        __nv_bfloat16 hi = __float2bfloat16(v);
        __nv_bfloat16 lo = __float2bfloat16(v - __bfloat162float(hi));
        long base = (long)bs * K3O + idx;
        g_Ao3[base] = hi; g_Ao3[base + INTER] = lo; g_Ao3[base + 2 * INTER] = hi;
    }
}

// ---------------- launch ------------------------------------------------------------
extern "C" void kernel_launch(void* const* d_in, const int* in_sizes, int n_in,
                              void* d_out, int out_size) {
    const float* hidden  = (const float*)d_in[0];
    const float* W_in    = (const float*)d_in[1];
    const float* conv_w  = (const float*)d_in[2];
    const float* conv_b  = (const float*)d_in[3];
    const float* dt_bias = (const float*)d_in[4];
    const float* A_log   = (const float*)d_in[5];
    const float* Dp      = (const float*)d_in[6];
    const float* norm_w  = (const float*)d_in[7];
    const float* W_out   = (const float*)d_in[8];
    float* out = (float*)d_out;

    cudaFuncSetAttribute(wmma_gemm, cudaFuncAttributeMaxDynamicSharedMemorySize, GEMM_SMEM);

    __nv_bfloat16 *Ah3, *Bh3, *Ao3, *Bo3;
    float* projp;
    cudaGetSymbolAddress((void**)&Ah3, g_Ah3);
    cudaGetSymbolAddress((void**)&Bh3, g_Bh3);
    cudaGetSymbolAddress((void**)&Ao3, g_Ao3);
    cudaGetSymbolAddress((void**)&Bo3, g_Bo3);
    cudaGetSymbolAddress((void**)&projp, g_proj);

    // 0) split conversions: A operands [hi,lo,hi]; B (weight) operands [hi,hi,lo]
    cvt3a_kernel<<<(BS * DMODEL) / 256, 256>>>(hidden, Ah3, BS, DMODEL);
    cvt3b_kernel<<<(PROJD_PAD * DMODEL) / 256, 256>>>(W_in, Bh3, PROJD, DMODEL);
    cvt3b_kernel<<<(DMODEL * INTER) / 256, 256>>>(W_out, Bo3, DMODEL, INTER);
    // 1) in-projection (wmma bf16-split), padded output stride PROJ_LD
    wmma_gemm<<<dim3(PROJD_PAD / 128, BS / 128), GEMM_THREADS, GEMM_SMEM>>>(
        Ah3, Bh3, projp, K3P, K3P / 64, PROJ_LD);
    // 2) dt + per-chunk cumsum of A*dt
    dtscan_kernel<<<BATCH * NHEADS * NCHUNK, 256>>>(dt_bias, A_log);
    // 3) depthwise conv + silu + split (+ x*dt)
    conv_kernel<<<dim3(BS, CONVD / 256), 256>>>(conv_w, conv_b);
    // 4) G = C @ B^T per (b,c)
    k_G_gemm<<<dim3(4, 4, BATCH * NCHUNK), 256>>>();
    // 5) per-chunk states
    states_kernel<<<BATCH * NCHUNK * NHEADS, 256>>>();
    // 6) inter-chunk recurrence -> prior states
    recur_kernel<<<BATCH * NHEADS, 256>>>();
    // 7) Y_diag + Y_off + D residual, p-split 2-way
    combine_kernel<<<BATCH * NCHUNK * NHEADS * 2, 256>>>(Dp);
    // 8) gated RMSNorm + bf16 A-split
    norm_kernel<<<BS, 256>>>(norm_w);
    // 9) out-projection (wmma bf16-split), N=768 exact
    wmma_gemm<<<dim3(DMODEL / 128, BS / 128), GEMM_THREADS, GEMM_SMEM>>>(
        Ao3, Bo3, out, K3O, K3O / 64, DMODEL);
}

// round 16
// speedup vs baseline: 1.0240x; 1.0240x over previous
#include <cuda_runtime.h>
#include <cuda_bf16.h>
#include <mma.h>
#include <cstdint>
using namespace nvcuda;

#define BATCH   2
#define SEQ     2048
#define DMODEL  768
#define INTER   1536
#define NHEADS  24
#define HEADDIM 64
#define DSTATE  128
#define CONVD   1792
#define PROJD   3352
#define CHUNK   256
#define NCHUNK  8
#define BS      (BATCH*SEQ)   // 4096

#define PROJD_PAD 3456        // 27*128 (padded N for proj GEMM)
#define PROJ_LD   PROJD_PAD   // row stride of g_proj
#define K3P (3*DMODEL)        // 2304
#define K3O (3*INTER)         // 4608

// ---------------- scratch (static device globals; no allocs allowed) ----------------
__device__ __align__(256) float g_proj [(long)BS*PROJ_LD];   // padded stride!
__device__ __align__(256) float g_xraw [(long)BS*INTER];
__device__ __align__(256) float g_xdisc[(long)BS*INTER];
__device__ __align__(256) float g_Bm   [(long)BS*DSTATE];
__device__ __align__(256) float g_Cm   [(long)BS*DSTATE];
__device__ float g_dt   [(long)BS*NHEADS];
__device__ float g_acum [(long)BATCH*NHEADS*NCHUNK*CHUNK];
__device__ __align__(256) float g_G    [(long)BATCH*NCHUNK*CHUNK*CHUNK];
__device__ __align__(256) float g_S    [(long)BATCH*NCHUNK*NHEADS*HEADDIM*DSTATE];
__device__ __align__(256) float g_pr   [(long)BATCH*NCHUNK*NHEADS*HEADDIM*DSTATE];
__device__ __align__(256) float g_y    [(long)BS*INTER];
// bf16 split operand buffers
__device__ __align__(256) __nv_bfloat16 g_Ah3[(long)BS*K3P];        // A: [hi, lo, hi]
__device__ __align__(256) __nv_bfloat16 g_Bh3[(long)PROJD_PAD*K3P]; // B: [hi, hi, lo]
__device__ __align__(256) __nv_bfloat16 g_Ao3[(long)BS*K3O];        // A: [hi, lo, hi]
__device__ __align__(256) __nv_bfloat16 g_Bo3[(long)DMODEL*K3O];    // B: [hi, hi, lo]

// ================= packed fp32x2 helpers (Blackwell FFMA2) ==========================
__device__ __forceinline__ uint64_t pack2(float x) {
    uint64_t r; asm("mov.b64 %0, {%1, %1};" : "=l"(r) : "f"(x)); return r;
}
__device__ __forceinline__ void fma2(uint64_t& d, uint64_t a, uint64_t b) {
    asm("fma.rn.f32x2 %0, %1, %2, %0;" : "+l"(d) : "l"(a), "l"(b));
}
__device__ __forceinline__ void mul2(uint64_t& d, uint64_t a) {
    asm("mul.rn.f32x2 %0, %0, %1;" : "+l"(d) : "l"(a));
}
__device__ __forceinline__ float2 unpack2(uint64_t v) {
    float2 f; asm("mov.b64 {%0, %1}, %2;" : "=f"(f.x), "=f"(f.y) : "l"(v)); return f;
}

// ================= cp.async helpers (sm_80+) ========================================
__device__ __forceinline__ uint32_t smem_u32(const void* p) {
    uint32_t a;
    asm("{ .reg .u64 t0; cvta.to.shared.u64 t0, %1; cvt.u32.u64 %0, t0; }"
        : "=r"(a) : "l"(p));
    return a;
}
#define CP16(dst, src) \
    asm volatile("cp.async.cg.shared.global [%0], [%1], 16;" :: "r"(dst), "l"(src))
#define CP_COMMIT() asm volatile("cp.async.commit_group;")
#define CP_WAIT(n)  asm volatile("cp.async.wait_group %0;" :: "n"(n))

// ================= wmma GEMM (R8-proven config, best measured) ======================
#define LDAE 72
#define TROWB 144
#define TILE_B (128*TROWB)             // 18432
#define GEMM_SMEM (4*TILE_B)           // 73728
#define GEMM_THREADS 256

__device__ __forceinline__ void stage_tile(uint32_t sa, uint32_t sb,
                                           const __nv_bfloat16* Ab,
                                           const __nv_bfloat16* Bb,
                                           int K3, int t) {
#pragma unroll
    for (int i = 0; i < 4; i++) {
        int id = i * GEMM_THREADS + t; // 0..1023 = 128 rows x 8 segs
        int row = id >> 3, seg = id & 7;
        uint32_t so = row * TROWB + seg * 16;
        CP16(sa + so, Ab + (long)row * K3 + seg * 8);
        CP16(sb + so, Bb + (long)row * K3 + seg * 8);
    }
}

__global__ void __launch_bounds__(GEMM_THREADS)
wmma_gemm(const __nv_bfloat16* __restrict__ A, const __nv_bfloat16* __restrict__ B,
          float* __restrict__ C, int K3, int KT, int ldc) {
    extern __shared__ char smem[];
    uint32_t sbase = smem_u32(smem);
    int t = threadIdx.x, wid = t >> 5;
    int wm = wid & 3, wn = wid >> 2;
    int m0 = blockIdx.y * 128, n0 = blockIdx.x * 128;

    wmma::fragment<wmma::accumulator, 16, 16, 16, float> cf[2][4];
#pragma unroll
    for (int mi = 0; mi < 2; mi++)
#pragma unroll
        for (int ni = 0; ni < 4; ni++) wmma::fill_fragment(cf[mi][ni], 0.f);

    stage_tile(sbase, sbase + TILE_B, A + (long)m0 * K3, B + (long)n0 * K3, K3, t);
    CP_COMMIT();

    for (int kt = 0; kt < KT; kt++) {
        int buf = kt & 1;
        if (kt + 1 < KT) {
            uint32_t sa = sbase + (buf ^ 1) * 2 * TILE_B;
            stage_tile(sa, sa + TILE_B,
                       A + (long)m0 * K3 + (kt + 1) * 64,
                       B + (long)n0 * K3 + (kt + 1) * 64, K3, t);
            CP_COMMIT();
            CP_WAIT(1);
        } else {
            CP_WAIT(0);
        }
        __syncthreads();

        const __nv_bfloat16* sa = (const __nv_bfloat16*)(smem + buf * 2 * TILE_B);
        const __nv_bfloat16* sb = (const __nv_bfloat16*)(smem + buf * 2 * TILE_B + TILE_B);
#pragma unroll
        for (int ks = 0; ks < 4; ks++) {
            wmma::fragment<wmma::matrix_a, 16, 16, 16, __nv_bfloat16, wmma::row_major> af[2];
            wmma::fragment<wmma::matrix_b, 16, 16, 16, __nv_bfloat16, wmma::col_major> bf[4];
#pragma unroll
            for (int mi = 0; mi < 2; mi++)
                wmma::load_matrix_sync(af[mi], sa + (wm * 32 + mi * 16) * LDAE + ks * 16, LDAE);
#pragma unroll
            for (int ni = 0; ni < 4; ni++)
                wmma::load_matrix_sync(bf[ni], sb + (wn * 64 + ni * 16) * LDAE + ks * 16, LDAE);
#pragma unroll
            for (int mi = 0; mi < 2; mi++)
#pragma unroll
                for (int ni = 0; ni < 4; ni++)
                    wmma::mma_sync(cf[mi][ni], af[mi], bf[ni], cf[mi][ni]);
        }
        __syncthreads();
    }

#pragma unroll
    for (int mi = 0; mi < 2; mi++)
#pragma unroll
        for (int ni = 0; ni < 4; ni++)
            wmma::store_matrix_sync(
                C + (long)(m0 + wm * 32 + mi * 16) * ldc + n0 + wn * 64 + ni * 16,
                cf[mi][ni], ldc, wmma::mem_row_major);
}

// ---------------- fp32 -> bf16 split conversions ------------------------------------
__global__ void cvt3a_kernel(const float* __restrict__ src, __nv_bfloat16* __restrict__ dst,
                             int rowsValid, int K) {
    long idx = (long)blockIdx.x * 256 + threadIdx.x;
    int r = (int)(idx / K), k = (int)(idx % K);
    float v = (r < rowsValid) ? src[(long)r * K + k] : 0.f;
    __nv_bfloat16 hi = __float2bfloat16(v);
    __nv_bfloat16 lo = __float2bfloat16(v - __bfloat162float(hi));
    long base = (long)r * (3 * K) + k;
    dst[base] = hi; dst[base + K] = lo; dst[base + 2 * K] = hi;
}
__global__ void cvt3b_kernel(const float* __restrict__ src, __nv_bfloat16* __restrict__ dst,
                             int rowsValid, int K) {
    long idx = (long)blockIdx.x * 256 + threadIdx.x;
    int r = (int)(idx / K), k = (int)(idx % K);
    float v = (r < rowsValid) ? src[(long)r * K + k] : 0.f;
    __nv_bfloat16 hi = __float2bfloat16(v);
    __nv_bfloat16 lo = __float2bfloat16(v - __bfloat162float(hi));
    long base = (long)r * (3 * K) + k;
    dst[base] = hi; dst[base + K] = hi; dst[base + 2 * K] = lo;
}

// ---------------- fp32 SGEMM (kept for the small G = C@B^T) -------------------------
__device__ __forceinline__ void sgemm_body(const float* __restrict__ A,
                                           const float* __restrict__ Bm,
                                           float* __restrict__ C,
                                           int M, int N, int Kd) {
    __shared__ float As[16][64];
    __shared__ float Bs[16][64];
    int t  = threadIdx.x;
    int tx = t & 15, ty = t >> 4;
    int row0 = blockIdx.y * 64, col0 = blockIdx.x * 64;
    int lr = t >> 2, lc = (t & 3) << 2;
    float acc[4][4] = {};
    for (int k0 = 0; k0 < Kd; k0 += 16) {
        int ar = row0 + lr;
        float4 av = make_float4(0.f, 0.f, 0.f, 0.f);
        if (ar < M) av = *(const float4*)(A + (long)ar * Kd + k0 + lc);
        As[lc][lr] = av.x; As[lc+1][lr] = av.y; As[lc+2][lr] = av.z; As[lc+3][lr] = av.w;
        int br = col0 + lr;
        float4 bv = make_float4(0.f, 0.f, 0.f, 0.f);
        if (br < N) bv = *(const float4*)(Bm + (long)br * Kd + k0 + lc);
        Bs[lc][lr] = bv.x; Bs[lc+1][lr] = bv.y; Bs[lc+2][lr] = bv.z; Bs[lc+3][lr] = bv.w;
        __syncthreads();
#pragma unroll
        for (int kk = 0; kk < 16; kk++) {
            float4 a4 = *(const float4*)&As[kk][ty * 4];
            float4 b4 = *(const float4*)&Bs[kk][tx * 4];
            float a[4] = {a4.x, a4.y, a4.z, a4.w};
            float b[4] = {b4.x, b4.y, b4.z, b4.w};
#pragma unroll
            for (int i = 0; i < 4; i++)
#pragma unroll
                for (int j = 0; j < 4; j++) acc[i][j] += a[i] * b[j];
        }
        __syncthreads();
    }
#pragma unroll
    for (int i = 0; i < 4; i++) {
        int r = row0 + ty * 4 + i;
        if (r >= M) continue;
#pragma unroll
        for (int j = 0; j < 4; j++) {
            int cc = col0 + tx * 4 + j;
            if (cc < N) C[(long)r * N + cc] = acc[i][j];
        }
    }
}
__global__ void k_G_gemm() {
    long off = (long)blockIdx.z * CHUNK * DSTATE;
    sgemm_body(g_Cm + off, g_Bm + off, g_G + (long)blockIdx.z * CHUNK * CHUNK,
               CHUNK, CHUNK, DSTATE);
}

// ---------------- dt (softplus+clip) + per-chunk inclusive cumsum of A*dt -----------
__global__ void dtscan_kernel(const float* __restrict__ dt_bias,
                              const float* __restrict__ A_log) {
    int bid = blockIdx.x;                 // ((b*NHEADS + h)*NCHUNK + c)
    int c = bid % NCHUNK;
    int h = (bid / NCHUNK) % NHEADS;
    int b = bid / (NCHUNK * NHEADS);
    int l = threadIdx.x;
    int s = c * CHUNK + l;
    float dtraw = g_proj[((long)(b * SEQ + s)) * PROJ_LD + (INTER + CONVD) + h];
    float xx = dtraw + dt_bias[h];
    float sp = (xx > 20.f) ? xx : log1pf(expf(xx));
    float dtv = fminf(fmaxf(sp, 0.001f), 0.1f);
    g_dt[(b * SEQ + s) * NHEADS + h] = dtv;
    float a = -expf(A_log[h]) * dtv;

    __shared__ float buf[256];
    buf[l] = a; __syncthreads();
    float v = a;
    for (int off = 1; off < 256; off <<= 1) {
        float add = (l >= off) ? buf[l - off] : 0.f;
        __syncthreads();
        v += add; buf[l] = v;
        __syncthreads();
    }
    g_acum[(long)bid * CHUNK + l] = v;
}

// ---------------- depthwise causal conv (K=4) + bias + silu, split outputs ---------
__global__ void conv_kernel(const float* __restrict__ conv_w,
                            const float* __restrict__ conv_b) {
    int bs = blockIdx.x;                  // 0..4095
    int ch = blockIdx.y * 256 + threadIdx.x;
    int b = bs >> 11, s = bs & 2047;
    float acc = conv_b[ch];
#pragma unroll
    for (int k = 0; k < 4; k++) {
        int sp = s - 3 + k;
        if (sp >= 0)
            acc += g_proj[((long)(b * SEQ + sp)) * PROJ_LD + INTER + ch] * conv_w[ch * 4 + k];
    }
    float v = acc / (1.f + __expf(-acc));   // silu
    if (ch < INTER) {
        g_xraw[(long)bs * INTER + ch] = v;
        int h = ch >> 6;
        g_xdisc[(long)bs * INTER + ch] = v * g_dt[bs * NHEADS + h];
    } else if (ch < INTER + DSTATE) {
        g_Bm[(long)bs * DSTATE + (ch - INTER)] = v;
    } else {
        g_Cm[(long)bs * DSTATE + (ch - INTER - DSTATE)] = v;
    }
}

// ---------------- chunk states: direct coalesced B loads (no bss staging) -----------
__global__ void states_kernel() {
    int bid = blockIdx.x;                 // ((b*NCHUNK + c)*NHEADS + h)
    int h = bid % NHEADS;
    int c = (bid / NHEADS) % NCHUNK;
    int b = bid / (NHEADS * NCHUNK);
    int t = threadIdx.x;
    __shared__ __align__(16) float xs[32 * 64];
    __shared__ float sdec[256];
    {
        const float* ac = g_acum + ((long)((b * NHEADS + h) * NCHUNK + c)) * CHUNK;
        float aend = ac[CHUNK - 1];
        sdec[t] = __expf(aend - ac[t]);
    }
    uint64_t acc2[16];
#pragma unroll
    for (int i = 0; i < 16; i++) acc2[i] = 0ull;
    int n = t & 127;
    int p0 = (t >> 7) << 5;               // 0 or 32
    long sBase = (long)(b * SEQ + c * CHUNK);
    for (int lt = 0; lt < 8; lt++) {
        __syncthreads();
#pragma unroll
        for (int it = 0; it < 8; it++) {  // x tile 32x64
            int e = it * 256 + t; int r = e >> 6, cc = e & 63;
            xs[e] = g_xdisc[(sBase + lt * 32 + r) * INTER + h * 64 + cc];
        }
        __syncthreads();
        const float* Bcol = g_Bm + (sBase + lt * 32) * DSTATE + n;  // coalesced per ll
#pragma unroll
        for (int ll = 0; ll < 32; ll++) {
            float bv = Bcol[(long)ll * DSTATE];
            uint64_t w2 = pack2(bv * sdec[lt * 32 + ll]);
            const ulonglong2* xr = (const ulonglong2*)&xs[ll * 64 + p0];
#pragma unroll
            for (int i = 0; i < 8; i++) {
                ulonglong2 v = xr[i];
                fma2(acc2[2 * i],     w2, v.x);
                fma2(acc2[2 * i + 1], w2, v.y);
            }
        }
    }
    float* outp = g_S + (long)bid * HEADDIM * DSTATE;
#pragma unroll
    for (int i = 0; i < 16; i++) {
        float2 f = unpack2(acc2[i]);
        outp[(p0 + 2 * i) * DSTATE + n]     = f.x;
        outp[(p0 + 2 * i + 1) * DSTATE + n] = f.y;
    }
}

// ---------------- chunk recurrence: P[c] = S[c-1] + exp(Aend[c-1]) * P[c-1] ---------
__global__ void recur_kernel() {
    int bid = blockIdx.x;                 // b*NHEADS + h
    int h = bid % NHEADS, b = bid / NHEADS;
    int t = threadIdx.x;
    float pr[32];
#pragma unroll
    for (int j = 0; j < 32; j++) pr[j] = 0.f;
    for (int c = 0; c < NCHUNK; c++) {
        long base = ((long)((b * NCHUNK + c) * NHEADS + h)) * (HEADDIM * DSTATE);
#pragma unroll
        for (int j = 0; j < 32; j++) g_pr[base + j * 256 + t] = pr[j];
        float lam = __expf(g_acum[((long)((b * NHEADS + h) * NCHUNK + c)) * CHUNK + 255]);
#pragma unroll
        for (int j = 0; j < 32; j++) pr[j] = g_S[base + j * 256 + t] + lam * pr[j];
    }
}

// ---------------- combine: per-thread-row C/G read DIRECTLY from global -------------
// Thread l owns output row l. C row (512 B contiguous) and G row segment (128 B =
// one line, L2-resident, shared by 24 head-blocks) are loaded straight into
// registers -- no smem round-trip, no staging barriers for them, and the l>=s0
// guard skips G reads for dead (upper-triangular) tiles. Only prior^T (Ps) and
// x (xs) tiles -- genuinely shared across threads -- go through smem.
__global__ void combine_kernel(const float* __restrict__ Dparam) {
    int bid = blockIdx.x;                 // ((b*NCHUNK + c)*NHEADS + h)
    int h = bid % NHEADS;
    int c = (bid / NHEADS) % NCHUNK;
    int b = bid / (NHEADS * NCHUNK);
    int l = threadIdx.x;
    __shared__ float sAc[256];
    __shared__ __align__(16) float sbuf[2048];   // Ps (16x64) / xs (32x64)
    __shared__ float tExp[32];
    const float* ac = g_acum + ((long)((b * NHEADS + h) * NCHUNK + c)) * CHUNK;
    sAc[l] = ac[l];

    uint64_t acc2[32];
#pragma unroll
    for (int i = 0; i < 32; i++) acc2[i] = 0ull;
    long sBase  = (long)(b * SEQ + c * CHUNK);
    long prBase = ((long)((b * NCHUNK + c) * NHEADS + h)) * (HEADDIM * DSTATE);
    const float* Crow = g_Cm + (sBase + l) * DSTATE;

    // ---- Phase 1: Y_off raw = C_row(l) . prior[p,:] ----
    float* Ps = sbuf;                     // [16][64]
    for (int nt = 0; nt < 8; nt++) {
        int n0 = nt * 16;
        __syncthreads();
#pragma unroll
        for (int it = 0; it < 4; it++) {  // prior^T tile 16x64
            int e = it * 256 + l; int nn = e >> 6, p = e & 63;
            Ps[nn * 64 + p] = g_pr[prBase + p * DSTATE + n0 + nn];
        }
        __syncthreads();
#pragma unroll
        for (int nq = 0; nq < 4; nq++) {
            float4 cv4 = *(const float4*)(Crow + n0 + nq * 4);
            float cva[4] = {cv4.x, cv4.y, cv4.z, cv4.w};
#pragma unroll
            for (int k = 0; k < 4; k++) {
                uint64_t cv2 = pack2(cva[k]);
                const ulonglong2* pp = (const ulonglong2*)&Ps[(nq * 4 + k) * 64];
#pragma unroll
                for (int i = 0; i < 16; i++) {
                    ulonglong2 v = pp[i];
                    fma2(acc2[2 * i],     cv2, v.x);
                    fma2(acc2[2 * i + 1], cv2, v.y);
                }
            }
        }
    }
    {   // scale by state_decay_out = exp(Acum[l])
        uint64_t el2 = pack2(__expf(sAc[l]));
#pragma unroll
        for (int i = 0; i < 32; i++) mul2(acc2[i], el2);
    }

    // ---- Phase 2: Y_diag, direct G-row reads, L factored per s-tile ----
    float* xs = sbuf;                     // [32][64]
    const float* Grow = g_G + ((long)(b * NCHUNK + c)) * CHUNK * CHUNK + (long)l * CHUNK;
    for (int st = 0; st < 8; st++) {
        int s0 = st * 32;
        __syncthreads();
#pragma unroll
        for (int it = 0; it < 8; it++) {  // x tile 32x64
            int e = it * 256 + l; int r = e >> 6, cc = e & 63;
            xs[e] = g_xdisc[(sBase + s0 + r) * INTER + h * 64 + cc];
        }
        if (l < 32) tExp[l] = __expf(sAc[s0] - sAc[s0 + l]);
        __syncthreads();
        if (l >= s0) {
            float basee = __expf(sAc[l] - sAc[s0]);
            int jmax = min(32, l - s0 + 1);
            for (int q = 0; q * 4 < jmax; q++) {
                float4 gv = *(const float4*)(Grow + s0 + q * 4);  // one line per thread
                float gva[4] = {gv.x, gv.y, gv.z, gv.w};
                int jend = min(4, jmax - q * 4);
                for (int jj = 0; jj < jend; jj++) {
                    int j = q * 4 + jj;
                    uint64_t w2 = pack2(gva[jj] * basee * tExp[j]);
                    const ulonglong2* xr = (const ulonglong2*)&xs[j * 64];
#pragma unroll
                    for (int i = 0; i < 16; i++) {
                        ulonglong2 v = xr[i];
                        fma2(acc2[2 * i],     w2, v.x);
                        fma2(acc2[2 * i + 1], w2, v.y);
                    }
                }
            }
        }
    }

    // ---- D residual + store (packed, LDG.128) ----
    uint64_t Dh2 = pack2(Dparam[h]);
    const ulonglong2* xr2 = (const ulonglong2*)(g_xraw + (sBase + l) * INTER + h * 64);
    ulonglong2* yout2 = (ulonglong2*)(g_y + (sBase + l) * INTER + h * 64);
#pragma unroll
    for (int i = 0; i < 16; i++) {
        ulonglong2 xv = xr2[i];
        uint64_t a0 = acc2[2 * i], a1 = acc2[2 * i + 1];
        fma2(a0, Dh2, xv.x);
        fma2(a1, Dh2, xv.y);
        ulonglong2 o; o.x = a0; o.y = a1;
        yout2[i] = o;
    }
}

// ---------------- gated RMSNorm -> bf16 A-split ([hi,lo,hi]) into g_Ao3 -------------
__global__ void norm_kernel(const float* __restrict__ norm_w) {
    int bs = blockIdx.x;
    int t = threadIdx.x;
    __shared__ float red[256];
    float yf[6];
    float ss = 0.f;
#pragma unroll
    for (int i = 0; i < 6; i++) {
        int idx = t + i * 256;
        float yv = g_y[(long)bs * INTER + idx];
        float gv = g_proj[(long)bs * PROJ_LD + idx];
        float f = yv * (gv / (1.f + __expf(-gv)));
        yf[i] = f; ss += f * f;
    }
    red[t] = ss; __syncthreads();
    for (int off = 128; off > 0; off >>= 1) {
        if (t < off) red[t] += red[t + off];
        __syncthreads();
    }
    float scale = rsqrtf(red[0] / (float)INTER + 1e-5f);
#pragma unroll
    for (int i = 0; i < 6; i++) {
        int idx = t + i * 256;
        float v = yf[i] * scale * norm_w[idx];
        __nv_bfloat16 hi = __float2bfloat16(v);
        __nv_bfloat16 lo = __float2bfloat16(v - __bfloat162float(hi));
        long base = (long)bs * K3O + idx;
        g_Ao3[base] = hi; g_Ao3[base + INTER] = lo; g_Ao3[base + 2 * INTER] = hi;
    }
}

// ---------------- launch ------------------------------------------------------------
extern "C" void kernel_launch(void* const* d_in, const int* in_sizes, int n_in,
                              void* d_out, int out_size) {
    const float* hidden  = (const float*)d_in[0];
    const float* W_in    = (const float*)d_in[1];
    const float* conv_w  = (const float*)d_in[2];
    const float* conv_b  = (const float*)d_in[3];
    const float* dt_bias = (const float*)d_in[4];
    const float* A_log   = (const float*)d_in[5];
    const float* Dp      = (const float*)d_in[6];
    const float* norm_w  = (const float*)d_in[7];
    const float* W_out   = (const float*)d_in[8];
    float* out = (float*)d_out;

    cudaFuncSetAttribute(wmma_gemm, cudaFuncAttributeMaxDynamicSharedMemorySize, GEMM_SMEM);

    __nv_bfloat16 *Ah3, *Bh3, *Ao3, *Bo3;
    float* projp;
    cudaGetSymbolAddress((void**)&Ah3, g_Ah3);
    cudaGetSymbolAddress((void**)&Bh3, g_Bh3);
    cudaGetSymbolAddress((void**)&Ao3, g_Ao3);
    cudaGetSymbolAddress((void**)&Bo3, g_Bo3);
    cudaGetSymbolAddress((void**)&projp, g_proj);

    // 0) split conversions: A operands [hi,lo,hi]; B (weight) operands [hi,hi,lo]
    cvt3a_kernel<<<(BS * DMODEL) / 256, 256>>>(hidden, Ah3, BS, DMODEL);
    cvt3b_kernel<<<(PROJD_PAD * DMODEL) / 256, 256>>>(W_in, Bh3, PROJD, DMODEL);
    cvt3b_kernel<<<(DMODEL * INTER) / 256, 256>>>(W_out, Bo3, DMODEL, INTER);
    // 1) in-projection (wmma bf16-split), padded output stride PROJ_LD
    wmma_gemm<<<dim3(PROJD_PAD / 128, BS / 128), GEMM_THREADS, GEMM_SMEM>>>(
        Ah3, Bh3, projp, K3P, K3P / 64, PROJ_LD);
    // 2) dt + per-chunk cumsum of A*dt
    dtscan_kernel<<<BATCH * NHEADS * NCHUNK, 256>>>(dt_bias, A_log);
    // 3) depthwise conv + silu + split (+ x*dt)
    conv_kernel<<<dim3(BS, CONVD / 256), 256>>>(conv_w, conv_b);
    // 4) G = C @ B^T per (b,c)
    k_G_gemm<<<dim3(4, 4, BATCH * NCHUNK), 256>>>();
    // 5) per-chunk states (direct B loads)
    states_kernel<<<BATCH * NCHUNK * NHEADS, 256>>>();
    // 6) inter-chunk recurrence -> prior states
    recur_kernel<<<BATCH * NHEADS, 256>>>();
    // 7) Y_diag + Y_off + D residual (direct C/G row loads)
    combine_kernel<<<BATCH * NCHUNK * NHEADS, 256>>>(Dp);
    // 8) gated RMSNorm + bf16 A-split
    norm_kernel<<<BS, 256>>>(norm_w);
    // 9) out-projection (wmma bf16-split), N=768 exact
    wmma_gemm<<<dim3(DMODEL / 128, BS / 128), GEMM_THREADS, GEMM_SMEM>>>(
        Ao3, Bo3, out, K3O, K3O / 64, DMODEL);
}

// round 17
// speedup vs baseline: 1.1718x; 1.1443x over previous
#include <cuda_runtime.h>
#include <cuda_bf16.h>
#include <mma.h>
#include <cstdint>
using namespace nvcuda;

#define BATCH   2
#define SEQ     2048
#define DMODEL  768
#define INTER   1536
#define NHEADS  24
#define HEADDIM 64
#define DSTATE  128
#define CONVD   1792
#define PROJD   3352
#define CHUNK   256
#define NCHUNK  8
#define BS      (BATCH*SEQ)   // 4096

#define PROJD_PAD 3456        // 27*128 (padded N for proj GEMM)
#define PROJ_LD   PROJD_PAD   // row stride of g_proj
#define K3P (3*DMODEL)        // 2304
#define K3O (3*INTER)         // 4608

// ---------------- scratch (static device globals; no allocs allowed) ----------------
__device__ __align__(256) float g_proj [(long)BS*PROJ_LD];   // padded stride!
__device__ __align__(256) float g_xraw [(long)BS*INTER];
__device__ __align__(256) float g_xdisc[(long)BS*INTER];
__device__ __align__(256) float g_Bm   [(long)BS*DSTATE];
__device__ __align__(256) float g_Cm   [(long)BS*DSTATE];
__device__ float g_dt   [(long)BS*NHEADS];
__device__ float g_acum [(long)BATCH*NHEADS*NCHUNK*CHUNK];
__device__ __align__(256) float g_G    [(long)BATCH*NCHUNK*CHUNK*CHUNK];
__device__ __align__(256) float g_S    [(long)BATCH*NCHUNK*NHEADS*HEADDIM*DSTATE];
__device__ __align__(256) float g_pr   [(long)BATCH*NCHUNK*NHEADS*HEADDIM*DSTATE];
__device__ __align__(256) float g_y    [(long)BS*INTER];
// bf16 split operand buffers
__device__ __align__(256) __nv_bfloat16 g_Ah3[(long)BS*K3P];        // A: [hi, lo, hi]
__device__ __align__(256) __nv_bfloat16 g_Bh3[(long)PROJD_PAD*K3P]; // B: [hi, hi, lo]
__device__ __align__(256) __nv_bfloat16 g_Ao3[(long)BS*K3O];        // A: [hi, lo, hi]
__device__ __align__(256) __nv_bfloat16 g_Bo3[(long)DMODEL*K3O];    // B: [hi, hi, lo]

// ================= cp.async helpers (sm_80+) ========================================
__device__ __forceinline__ uint32_t smem_u32(const void* p) {
    uint32_t a;
    asm("{ .reg .u64 t0; cvta.to.shared.u64 t0, %1; cvt.u32.u64 %0, t0; }"
        : "=r"(a) : "l"(p));
    return a;
}
#define CP16(dst, src) \
    asm volatile("cp.async.cg.shared.global [%0], [%1], 16;" :: "r"(dst), "l"(src))
#define CP_COMMIT() asm volatile("cp.async.commit_group;")
#define CP_WAIT(n)  asm volatile("cp.async.wait_group %0;" :: "n"(n))

// ================= wmma GEMM (R8-proven config, best measured) ======================
#define LDAE 72
#define TROWB 144
#define TILE_B (128*TROWB)             // 18432
#define GEMM_SMEM (4*TILE_B)           // 73728
#define GEMM_THREADS 256

__device__ __forceinline__ void stage_tile(uint32_t sa, uint32_t sb,
                                           const __nv_bfloat16* Ab,
                                           const __nv_bfloat16* Bb,
                                           int K3, int t) {
#pragma unroll
    for (int i = 0; i < 4; i++) {
        int id = i * GEMM_THREADS + t; // 0..1023 = 128 rows x 8 segs
        int row = id >> 3, seg = id & 7;
        uint32_t so = row * TROWB + seg * 16;
        CP16(sa + so, Ab + (long)row * K3 + seg * 8);
        CP16(sb + so, Bb + (long)row * K3 + seg * 8);
    }
}

__global__ void __launch_bounds__(GEMM_THREADS)
wmma_gemm(const __nv_bfloat16* __restrict__ A, const __nv_bfloat16* __restrict__ B,
          float* __restrict__ C, int K3, int KT, int ldc) {
    extern __shared__ char smem[];
    uint32_t sbase = smem_u32(smem);
    int t = threadIdx.x, wid = t >> 5;
    int wm = wid & 3, wn = wid >> 2;
    int m0 = blockIdx.y * 128, n0 = blockIdx.x * 128;

    wmma::fragment<wmma::accumulator, 16, 16, 16, float> cf[2][4];
#pragma unroll
    for (int mi = 0; mi < 2; mi++)
#pragma unroll
        for (int ni = 0; ni < 4; ni++) wmma::fill_fragment(cf[mi][ni], 0.f);

    stage_tile(sbase, sbase + TILE_B, A + (long)m0 * K3, B + (long)n0 * K3, K3, t);
    CP_COMMIT();

    for (int kt = 0; kt < KT; kt++) {
        int buf = kt & 1;
        if (kt + 1 < KT) {
            uint32_t sa = sbase + (buf ^ 1) * 2 * TILE_B;
            stage_tile(sa, sa + TILE_B,
                       A + (long)m0 * K3 + (kt + 1) * 64,
                       B + (long)n0 * K3 + (kt + 1) * 64, K3, t);
            CP_COMMIT();
            CP_WAIT(1);
        } else {
            CP_WAIT(0);
        }
        __syncthreads();

        const __nv_bfloat16* sa = (const __nv_bfloat16*)(smem + buf * 2 * TILE_B);
        const __nv_bfloat16* sb = (const __nv_bfloat16*)(smem + buf * 2 * TILE_B + TILE_B);
#pragma unroll
        for (int ks = 0; ks < 4; ks++) {
            wmma::fragment<wmma::matrix_a, 16, 16, 16, __nv_bfloat16, wmma::row_major> af[2];
            wmma::fragment<wmma::matrix_b, 16, 16, 16, __nv_bfloat16, wmma::col_major> bf[4];
#pragma unroll
            for (int mi = 0; mi < 2; mi++)
                wmma::load_matrix_sync(af[mi], sa + (wm * 32 + mi * 16) * LDAE + ks * 16, LDAE);
#pragma unroll
            for (int ni = 0; ni < 4; ni++)
                wmma::load_matrix_sync(bf[ni], sb + (wn * 64 + ni * 16) * LDAE + ks * 16, LDAE);
#pragma unroll
            for (int mi = 0; mi < 2; mi++)
#pragma unroll
                for (int ni = 0; ni < 4; ni++)
                    wmma::mma_sync(cf[mi][ni], af[mi], bf[ni], cf[mi][ni]);
        }
        __syncthreads();
    }

#pragma unroll
    for (int mi = 0; mi < 2; mi++)
#pragma unroll
        for (int ni = 0; ni < 4; ni++)
            wmma::store_matrix_sync(
                C + (long)(m0 + wm * 32 + mi * 16) * ldc + n0 + wn * 64 + ni * 16,
                cf[mi][ni], ldc, wmma::mem_row_major);
}

// ---------------- fp32 -> bf16 split conversions ------------------------------------
__global__ void cvt3a_kernel(const float* __restrict__ src, __nv_bfloat16* __restrict__ dst,
                             int rowsValid, int K) {
    long idx = (long)blockIdx.x * 256 + threadIdx.x;
    int r = (int)(idx / K), k = (int)(idx % K);
    float v = (r < rowsValid) ? src[(long)r * K + k] : 0.f;
    __nv_bfloat16 hi = __float2bfloat16(v);
    __nv_bfloat16 lo = __float2bfloat16(v - __bfloat162float(hi));
    long base = (long)r * (3 * K) + k;
    dst[base] = hi; dst[base + K] = lo; dst[base + 2 * K] = hi;
}
__global__ void cvt3b_kernel(const float* __restrict__ src, __nv_bfloat16* __restrict__ dst,
                             int rowsValid, int K) {
    long idx = (long)blockIdx.x * 256 + threadIdx.x;
    int r = (int)(idx / K), k = (int)(idx % K);
    float v = (r < rowsValid) ? src[(long)r * K + k] : 0.f;
    __nv_bfloat16 hi = __float2bfloat16(v);
    __nv_bfloat16 lo = __float2bfloat16(v - __bfloat162float(hi));
    long base = (long)r * (3 * K) + k;
    dst[base] = hi; dst[base + K] = hi; dst[base + 2 * K] = lo;
}

// ---------------- fp32 SGEMM (kept for the small G = C@B^T) -------------------------
__device__ __forceinline__ void sgemm_body(const float* __restrict__ A,
                                           const float* __restrict__ Bm,
                                           float* __restrict__ C,
                                           int M, int N, int Kd) {
    __shared__ float As[16][64];
    __shared__ float Bs[16][64];
    int t  = threadIdx.x;
    int tx = t & 15, ty = t >> 4;
    int row0 = blockIdx.y * 64, col0 = blockIdx.x * 64;
    int lr = t >> 2, lc = (t & 3) << 2;
    float acc[4][4] = {};
    for (int k0 = 0; k0 < Kd; k0 += 16) {
        int ar = row0 + lr;
        float4 av = make_float4(0.f, 0.f, 0.f, 0.f);
        if (ar < M) av = *(const float4*)(A + (long)ar * Kd + k0 + lc);
        As[lc][lr] = av.x; As[lc+1][lr] = av.y; As[lc+2][lr] = av.z; As[lc+3][lr] = av.w;
        int br = col0 + lr;
        float4 bv = make_float4(0.f, 0.f, 0.f, 0.f);
        if (br < N) bv = *(const float4*)(Bm + (long)br * Kd + k0 + lc);
        Bs[lc][lr] = bv.x; Bs[lc+1][lr] = bv.y; Bs[lc+2][lr] = bv.z; Bs[lc+3][lr] = bv.w;
        __syncthreads();
#pragma unroll
        for (int kk = 0; kk < 16; kk++) {
            float4 a4 = *(const float4*)&As[kk][ty * 4];
            float4 b4 = *(const float4*)&Bs[kk][tx * 4];
            float a[4] = {a4.x, a4.y, a4.z, a4.w};
            float b[4] = {b4.x, b4.y, b4.z, b4.w};
#pragma unroll
            for (int i = 0; i < 4; i++)
#pragma unroll
                for (int j = 0; j < 4; j++) acc[i][j] += a[i] * b[j];
        }
        __syncthreads();
    }
#pragma unroll
    for (int i = 0; i < 4; i++) {
        int r = row0 + ty * 4 + i;
        if (r >= M) continue;
#pragma unroll
        for (int j = 0; j < 4; j++) {
            int cc = col0 + tx * 4 + j;
            if (cc < N) C[(long)r * N + cc] = acc[i][j];
        }
    }
}
__global__ void k_G_gemm() {
    long off = (long)blockIdx.z * CHUNK * DSTATE;
    sgemm_body(g_Cm + off, g_Bm + off, g_G + (long)blockIdx.z * CHUNK * CHUNK,
               CHUNK, CHUNK, DSTATE);
}

// ---------------- dt (softplus+clip) + per-chunk inclusive cumsum of A*dt -----------
__global__ void dtscan_kernel(const float* __restrict__ dt_bias,
                              const float* __restrict__ A_log) {
    int bid = blockIdx.x;                 // ((b*NHEADS + h)*NCHUNK + c)
    int c = bid % NCHUNK;
    int h = (bid / NCHUNK) % NHEADS;
    int b = bid / (NCHUNK * NHEADS);
    int l = threadIdx.x;
    int s = c * CHUNK + l;
    float dtraw = g_proj[((long)(b * SEQ + s)) * PROJ_LD + (INTER + CONVD) + h];
    float xx = dtraw + dt_bias[h];
    float sp = (xx > 20.f) ? xx : log1pf(expf(xx));
    float dtv = fminf(fmaxf(sp, 0.001f), 0.1f);
    g_dt[(b * SEQ + s) * NHEADS + h] = dtv;
    float a = -expf(A_log[h]) * dtv;

    __shared__ float buf[256];
    buf[l] = a; __syncthreads();
    float v = a;
    for (int off = 1; off < 256; off <<= 1) {
        float add = (l >= off) ? buf[l - off] : 0.f;
        __syncthreads();
        v += add; buf[l] = v;
        __syncthreads();
    }
    g_acum[(long)bid * CHUNK + l] = v;
}

// ---------------- depthwise causal conv: 4 outputs/thread (7 reads vs 16) -----------
__global__ void conv_kernel(const float* __restrict__ conv_w,
                            const float* __restrict__ conv_b) {
    int sg = blockIdx.x;                  // 0..BS/4-1 ; s0..s0+3 in same batch (SEQ%4==0)
    int ch = blockIdx.y * 256 + threadIdx.x;
    int bs0 = sg * 4;
    int b = bs0 >> 11, s0 = bs0 & 2047;
    float w0 = conv_w[ch * 4],     w1 = conv_w[ch * 4 + 1];
    float w2 = conv_w[ch * 4 + 2], w3 = conv_w[ch * 4 + 3];
    float bias = conv_b[ch];
    float x[7];
#pragma unroll
    for (int i = 0; i < 7; i++) {
        int sp = s0 - 3 + i;
        x[i] = (sp >= 0 && sp < SEQ) ? g_proj[((long)(b * SEQ + sp)) * PROJ_LD + INTER + ch] : 0.f;
    }
#pragma unroll
    for (int k = 0; k < 4; k++) {
        int bs = bs0 + k;
        // same summation order as reference loop: bias + w0*x[-3] + w1*x[-2] + w2*x[-1] + w3*x[0]
        float acc = bias;
        acc += x[k] * w0;
        acc += x[k + 1] * w1;
        acc += x[k + 2] * w2;
        acc += x[k + 3] * w3;
        float v = acc / (1.f + __expf(-acc));   // silu
        if (ch < INTER) {
            g_xraw[(long)bs * INTER + ch] = v;
            int h = ch >> 6;
            g_xdisc[(long)bs * INTER + ch] = v * g_dt[bs * NHEADS + h];
        } else if (ch < INTER + DSTATE) {
            g_Bm[(long)bs * DSTATE + (ch - INTER)] = v;
        } else {
            g_Cm[(long)bs * DSTATE + (ch - INTER - DSTATE)] = v;
        }
    }
}

// ---------------- chunk states (R8-proven version) ----------------------------------
__global__ void states_kernel() {
    int bid = blockIdx.x;                 // ((b*NCHUNK + c)*NHEADS + h)
    int h = bid % NHEADS;
    int c = (bid / NHEADS) % NCHUNK;
    int b = bid / (NHEADS * NCHUNK);
    int t = threadIdx.x;
    __shared__ float xs[32 * 64];
    __shared__ float bss[32 * 128];
    __shared__ float sdec[256];
    {
        const float* ac = g_acum + ((long)((b * NHEADS + h) * NCHUNK + c)) * CHUNK;
        float aend = ac[CHUNK - 1];
        sdec[t] = __expf(aend - ac[t]);
    }
    float acc[32];
#pragma unroll
    for (int i = 0; i < 32; i++) acc[i] = 0.f;
    int n = t & 127;
    int p0 = (t >> 7) << 5;               // 0 or 32
    long sBase = (long)(b * SEQ + c * CHUNK);
    for (int lt = 0; lt < 8; lt++) {
        __syncthreads();
#pragma unroll
        for (int it = 0; it < 8; it++) {  // x tile 32x64
            int e = it * 256 + t; int r = e >> 6, cc = e & 63;
            xs[e] = g_xdisc[(sBase + lt * 32 + r) * INTER + h * 64 + cc];
        }
#pragma unroll
        for (int it = 0; it < 16; it++) { // B tile 32x128
            int e = it * 256 + t; int r = e >> 7, cc = e & 127;
            bss[e] = g_Bm[(sBase + lt * 32 + r) * DSTATE + cc];
        }
        __syncthreads();
#pragma unroll
        for (int ll = 0; ll < 32; ll++) {
            float w = bss[ll * 128 + n] * sdec[lt * 32 + ll];
            const float* xr = &xs[ll * 64 + p0];
#pragma unroll
            for (int pi = 0; pi < 32; pi += 4) {
                float4 xv = *(const float4*)(xr + pi);
                acc[pi]     += w * xv.x; acc[pi + 1] += w * xv.y;
                acc[pi + 2] += w * xv.z; acc[pi + 3] += w * xv.w;
            }
        }
    }
    float* outp = g_S + (long)bid * HEADDIM * DSTATE;
#pragma unroll
    for (int pi = 0; pi < 32; pi++) outp[(p0 + pi) * DSTATE + n] = acc[pi];
}

// ---------------- chunk recurrence, j-split 4-way (grid 48 -> 192 blocks) -----------
__global__ void recur_kernel() {
    int bid = blockIdx.x;                 // (b*NHEADS + h)*4 + jq
    int jq = bid & 3;
    int rest = bid >> 2;
    int h = rest % NHEADS, b = rest / NHEADS;
    int t = threadIdx.x;
    float pr[8];
#pragma unroll
    for (int j = 0; j < 8; j++) pr[j] = 0.f;
    for (int c = 0; c < NCHUNK; c++) {
        long base = ((long)((b * NCHUNK + c) * NHEADS + h)) * (HEADDIM * DSTATE)
                  + (long)jq * 8 * 256;
#pragma unroll
        for (int j = 0; j < 8; j++) g_pr[base + j * 256 + t] = pr[j];
        float lam = __expf(g_acum[((long)((b * NHEADS + h) * NCHUNK + c)) * CHUNK + 255]);
#pragma unroll
        for (int j = 0; j < 8; j++) pr[j] = g_S[base + j * 256 + t] + lam * pr[j];
    }
}

// ---------------- combine (R8-proven version) ---------------------------------------
__global__ void combine_kernel(const float* __restrict__ Dparam) {
    int bid = blockIdx.x;                 // ((b*NCHUNK + c)*NHEADS + h)
    int h = bid % NHEADS;
    int c = (bid / NHEADS) % NCHUNK;
    int b = bid / (NHEADS * NCHUNK);
    int l = threadIdx.x;
    __shared__ float sAc[256];
    __shared__ float sbuf[10496];
    __shared__ float tExp[32];
    const float* ac = g_acum + ((long)((b * NHEADS + h) * NCHUNK + c)) * CHUNK;
    sAc[l] = ac[l];
    __syncthreads();

    float acc[64];
#pragma unroll
    for (int p = 0; p < 64; p++) acc[p] = 0.f;
    long sBase  = (long)(b * SEQ + c * CHUNK);
    long prBase = ((long)((b * NCHUNK + c) * NHEADS + h)) * (HEADDIM * DSTATE);

    // ---- Phase 1: Y_off raw = C_row(l) . prior[p,:] ----
    float* Cs = sbuf;                     // [256][17]
    float* Ps = sbuf + 4352;              // [16][64]
    for (int nt = 0; nt < 8; nt++) {
        int n0 = nt * 16;
        __syncthreads();
#pragma unroll
        for (int it = 0; it < 16; it++) { // C tile 256x16
            int e = it * 256 + l; int r = e >> 4, cc = e & 15;
            Cs[r * 17 + cc] = g_Cm[(sBase + r) * DSTATE + n0 + cc];
        }
#pragma unroll
        for (int it = 0; it < 4; it++) {  // prior^T tile 16x64
            int e = it * 256 + l; int nn = e >> 6, p = e & 63;
            Ps[nn * 64 + p] = g_pr[prBase + p * DSTATE + n0 + nn];
        }
        __syncthreads();
#pragma unroll
        for (int nn = 0; nn < 16; nn++) {
            float cv = Cs[l * 17 + nn];
            const float* pp = &Ps[nn * 64];
#pragma unroll
            for (int p = 0; p < 64; p += 4) {
                float4 v = *(const float4*)(pp + p);
                acc[p]     += cv * v.x; acc[p + 1] += cv * v.y;
                acc[p + 2] += cv * v.z; acc[p + 3] += cv * v.w;
            }
        }
    }
    {   // scale by state_decay_out = exp(Acum[l])
        float el = __expf(sAc[l]);
#pragma unroll
        for (int p = 0; p < 64; p++) acc[p] *= el;
    }

    // ---- Phase 2: Y_diag, L factored per s-tile to avoid per-pair exp ----
    float* Gs = sbuf;                     // [256][33]
    float* xs = sbuf + 8448;              // [32][64]
    const float* Grow = g_G + ((long)(b * NCHUNK + c)) * CHUNK * CHUNK;
    for (int st = 0; st < 8; st++) {
        int s0 = st * 32;
        __syncthreads();
#pragma unroll
        for (int it = 0; it < 32; it++) { // G tile 256x32
            int e = it * 256 + l; int r = e >> 5, cc = e & 31;
            Gs[r * 33 + cc] = Grow[(long)r * CHUNK + s0 + cc];
        }
#pragma unroll
        for (int it = 0; it < 8; it++) {  // x tile 32x64
            int e = it * 256 + l; int r = e >> 6, cc = e & 63;
            xs[e] = g_xdisc[(sBase + s0 + r) * INTER + h * 64 + cc];
        }
        if (l < 32) tExp[l] = __expf(sAc[s0] - sAc[s0 + l]);
        __syncthreads();
        if (l >= s0) {
            float basee = __expf(sAc[l] - sAc[s0]);
            int jmax = min(32, l - s0 + 1);
            for (int j = 0; j < jmax; j++) {
                float w = Gs[l * 33 + j] * basee * tExp[j];
                const float* xr = &xs[j * 64];
#pragma unroll
                for (int p = 0; p < 64; p += 4) {
                    float4 v = *(const float4*)(xr + p);
                    acc[p]     += w * v.x; acc[p + 1] += w * v.y;
                    acc[p + 2] += w * v.z; acc[p + 3] += w * v.w;
                }
            }
        }
    }

    // ---- D residual + store ----
    float Dh = Dparam[h];
    const float* xr = g_xraw + (sBase + l) * INTER + h * 64;
    float* yout = g_y + (sBase + l) * INTER + h * 64;
#pragma unroll
    for (int p = 0; p < 64; p += 4) {
        float4 xv = *(const float4*)(xr + p);
        float4 o;
        o.x = acc[p]     + Dh * xv.x;
        o.y = acc[p + 1] + Dh * xv.y;
        o.z = acc[p + 2] + Dh * xv.z;
        o.w = acc[p + 3] + Dh * xv.w;
        *(float4*)(yout + p) = o;
    }
}

// ---------------- gated RMSNorm -> bf16 A-split ([hi,lo,hi]) into g_Ao3 -------------
__global__ void norm_kernel(const float* __restrict__ norm_w) {
    int bs = blockIdx.x;
    int t = threadIdx.x;
    __shared__ float red[256];
    float yf[6];
    float ss = 0.f;
#pragma unroll
    for (int i = 0; i < 6; i++) {
        int idx = t + i * 256;
        float yv = g_y[(long)bs * INTER + idx];
        float gv = g_proj[(long)bs * PROJ_LD + idx];
        float f = yv * (gv / (1.f + __expf(-gv)));
        yf[i] = f; ss += f * f;
    }
    red[t] = ss; __syncthreads();
    for (int off = 128; off > 0; off >>= 1) {
        if (t < off) red[t] += red[t + off];
        __syncthreads();
    }
    float scale = rsqrtf(red[0] / (float)INTER + 1e-5f);
#pragma unroll
    for (int i = 0; i < 6; i++) {
        int idx = t + i * 256;
        float v = yf[i] * scale * norm_w[idx];
        __nv_bfloat16 hi = __float2bfloat16(v);
        __nv_bfloat16 lo = __float2bfloat16(v - __bfloat162float(hi));
        long base = (long)bs * K3O + idx;
        g_Ao3[base] = hi; g_Ao3[base + INTER] = lo; g_Ao3[base + 2 * INTER] = hi;
    }
}

// ---------------- launch ------------------------------------------------------------
extern "C" void kernel_launch(void* const* d_in, const int* in_sizes, int n_in,
                              void* d_out, int out_size) {
    const float* hidden  = (const float*)d_in[0];
    const float* W_in    = (const float*)d_in[1];
    const float* conv_w  = (const float*)d_in[2];
    const float* conv_b  = (const float*)d_in[3];
    const float* dt_bias = (const float*)d_in[4];
    const float* A_log   = (const float*)d_in[5];
    const float* Dp      = (const float*)d_in[6];
    const float* norm_w  = (const float*)d_in[7];
    const float* W_out   = (const float*)d_in[8];
    float* out = (float*)d_out;

    cudaFuncSetAttribute(wmma_gemm, cudaFuncAttributeMaxDynamicSharedMemorySize, GEMM_SMEM);

    __nv_bfloat16 *Ah3, *Bh3, *Ao3, *Bo3;
    float* projp;
    cudaGetSymbolAddress((void**)&Ah3, g_Ah3);
    cudaGetSymbolAddress((void**)&Bh3, g_Bh3);
    cudaGetSymbolAddress((void**)&Ao3, g_Ao3);
    cudaGetSymbolAddress((void**)&Bo3, g_Bo3);
    cudaGetSymbolAddress((void**)&projp, g_proj);

    // 0) split conversions: A operands [hi,lo,hi]; B (weight) operands [hi,hi,lo]
    cvt3a_kernel<<<(BS * DMODEL) / 256, 256>>>(hidden, Ah3, BS, DMODEL);
    cvt3b_kernel<<<(PROJD_PAD * DMODEL) / 256, 256>>>(W_in, Bh3, PROJD, DMODEL);
    cvt3b_kernel<<<(DMODEL * INTER) / 256, 256>>>(W_out, Bo3, DMODEL, INTER);
    // 1) in-projection (wmma bf16-split), padded output stride PROJ_LD
    wmma_gemm<<<dim3(PROJD_PAD / 128, BS / 128), GEMM_THREADS, GEMM_SMEM>>>(
        Ah3, Bh3, projp, K3P, K3P / 64, PROJ_LD);
    // 2) dt + per-chunk cumsum of A*dt
    dtscan_kernel<<<BATCH * NHEADS * NCHUNK, 256>>>(dt_bias, A_log);
    // 3) depthwise conv + silu + split, 4 outputs/thread
    conv_kernel<<<dim3(BS / 4, CONVD / 256), 256>>>(conv_w, conv_b);
    // 4) G = C @ B^T per (b,c)
    k_G_gemm<<<dim3(4, 4, BATCH * NCHUNK), 256>>>();
    // 5) per-chunk states
    states_kernel<<<BATCH * NCHUNK * NHEADS, 256>>>();
    // 6) inter-chunk recurrence -> prior states (j-split 4-way, full-chip grid)
    recur_kernel<<<BATCH * NHEADS * 4, 256>>>();
    // 7) Y_diag + Y_off + D residual
    combine_kernel<<<BATCH * NCHUNK * NHEADS, 256>>>(Dp);
    // 8) gated RMSNorm + bf16 A-split
    norm_kernel<<<BS, 256>>>(norm_w);
    // 9) out-projection (wmma bf16-split), N=768 exact
    wmma_gemm<<<dim3(DMODEL / 128, BS / 128), GEMM_THREADS, GEMM_SMEM>>>(
        Ao3, Bo3, out, K3O, K3O / 64, DMODEL);
}